// round 7
// baseline (speedup 1.0000x reference)
#include <cuda_runtime.h>
#include <cuda_fp16.h>
#include <cstdint>

// ---------------------------------------------------------------------------
// B=32, T=4096, K=1024 (2H), N=512 (DFF)
// HMMA GEMM, single N-pass: CTA M64 x N512, 256 thr, 8 warps (each M64 x N64).
// ---------------------------------------------------------------------------
#define BATCH   32
#define TSEQ    4096
#define KDIM    1024
#define NDFF    512
#define MTILE   64
#define KCH     32
#define NCHUNKS 32
#define NTILES  (TSEQ / MTILE)     // 64
#define NCTAS   (BATCH * NTILES)   // 2048

__device__ __align__(128) __half g_Uh[NDFF * KDIM];             // 1 MB fp16 U [f][e]
__device__ __align__(128) float  g_ws[BATCH * NDFF];
__device__ __align__(128) float  g_partial[NCTAS * KDIM];       // 8 MB
__device__ int g_cnt[BATCH];

// Shared layout (bytes)
#define SM_WS   0                       // 512 f
#define SM_V    2048                    // 512 f
#define SM_EN   4096                    // 8*64 f
#define SM_ENF  6144                    // 64 f
#define SM_FLAG 6400                    // int
#define SM_A    8192                    // 3 stages x 4096
#define SM_B    20480                   // 3 stages x 32768
#define SMEM_TOTAL 118784

#define SWZ(off) ((uint32_t)(off) ^ ((((uint32_t)(off)) >> 3) & 0x70u))

__device__ __forceinline__ uint32_t smem_u32(const void* p) {
    uint32_t a;
    asm("{ .reg .u64 t; cvta.to.shared.u64 t, %1; cvt.u32.u64 %0, t; }"
        : "=r"(a) : "l"(p));
    return a;
}
__device__ __forceinline__ void cp_async16(uint32_t dst, const void* src) {
    asm volatile("cp.async.cg.shared.global [%0], [%1], 16;"
                 :: "r"(dst), "l"(src) : "memory");
}
#define CP_COMMIT() asm volatile("cp.async.commit_group;" ::: "memory")
#define CP_WAIT1()  asm volatile("cp.async.wait_group 1;" ::: "memory")

__device__ __forceinline__ void ldsm4(uint32_t& r0, uint32_t& r1, uint32_t& r2,
                                      uint32_t& r3, uint32_t addr) {
    asm volatile("ldmatrix.sync.aligned.m8n8.x4.shared.b16 {%0,%1,%2,%3}, [%4];"
                 : "=r"(r0), "=r"(r1), "=r"(r2), "=r"(r3) : "r"(addr));
}
__device__ __forceinline__ void mma16816(float* c, const uint32_t* a,
                                         uint32_t b0, uint32_t b1) {
    asm volatile(
        "mma.sync.aligned.m16n8k16.row.col.f32.f16.f16.f32 "
        "{%0,%1,%2,%3}, {%4,%5,%6,%7}, {%8,%9}, {%0,%1,%2,%3};"
        : "+f"(c[0]), "+f"(c[1]), "+f"(c[2]), "+f"(c[3])
        : "r"(a[0]), "r"(a[1]), "r"(a[2]), "r"(a[3]), "r"(b0), "r"(b1));
}
__device__ __forceinline__ uint4 cvt8(const float4& x, const float4& y) {
    uint4 u; __half2 t;
    t = __floats2half2_rn(x.x, x.y); u.x = *(uint32_t*)&t;
    t = __floats2half2_rn(x.z, x.w); u.y = *(uint32_t*)&t;
    t = __floats2half2_rn(y.x, y.y); u.z = *(uint32_t*)&t;
    t = __floats2half2_rn(y.z, y.w); u.w = *(uint32_t*)&t;
    return u;
}

// ---------------------------------------------------------------------------
// Fused prep: blocks 0..511 convU, 512..575 ws, 576 zero counters
// ---------------------------------------------------------------------------
__global__ void k_prep(const float* __restrict__ Uw, const float* __restrict__ s,
                       const float* __restrict__ W,  const float* __restrict__ Wb,
                       const float* __restrict__ Ub) {
    int blk = blockIdx.x;
    int tid = threadIdx.x;
    if (blk < 512) {
        int i = blk * 256 + tid;
        float4 v = reinterpret_cast<const float4*>(Uw)[i];
        __half2 p0 = __floats2half2_rn(v.x, v.y);
        __half2 p1 = __floats2half2_rn(v.z, v.w);
        uint2 u;
        u.x = *reinterpret_cast<uint32_t*>(&p0);
        u.y = *reinterpret_cast<uint32_t*>(&p1);
        *reinterpret_cast<uint2*>(&g_Uh[i * 4]) = u;
    } else if (blk < 576) {
        __shared__ float ssh[512];
        int q = blk - 512;
        int b = q >> 1;
        int f = ((q & 1) << 8) + tid;
        ssh[tid]       = s[b * 512 + tid];
        ssh[tid + 256] = s[b * 512 + tid + 256];
        __syncthreads();
        float acc = Wb[f] + Ub[f];
        const float4* Wr = reinterpret_cast<const float4*>(W + (size_t)f * 512);
#pragma unroll 4
        for (int e4 = 0; e4 < 128; e4++) {
            float4 w = Wr[e4];
            acc = fmaf(ssh[e4 * 4 + 0], w.x, acc);
            acc = fmaf(ssh[e4 * 4 + 1], w.y, acc);
            acc = fmaf(ssh[e4 * 4 + 2], w.z, acc);
            acc = fmaf(ssh[e4 * 4 + 3], w.w, acc);
        }
        g_ws[b * 512 + f] = acc;
    } else {
        if (tid < BATCH) g_cnt[tid] = 0;
    }
}

// ---------------------------------------------------------------------------
// Main kernel: 256 threads, 8 warps, warp tile M64 x N64, single N-pass.
// Packed smem rows: two 64B k-rows per 128B smem row, SW128-swizzled.
// ---------------------------------------------------------------------------
__global__ __launch_bounds__(256, 1)
void k_main(const float* __restrict__ h, const float* __restrict__ V,
            const float* __restrict__ Vb, float* __restrict__ out) {
    extern __shared__ char smem[];
    const uint32_t sb = smem_u32(smem);
    const int tid  = threadIdx.x;
    const int wid  = tid >> 5;     // = ng, 0..7 (N64 slice)
    const int lane = tid & 31;
    const int b    = blockIdx.x >> 6;

    float* ws_s  = reinterpret_cast<float*>(smem + SM_WS);
    float* V_s   = reinterpret_cast<float*>(smem + SM_V);
    float* en_s  = reinterpret_cast<float*>(smem + SM_EN);
    float* enf_s = reinterpret_cast<float*>(smem + SM_ENF);
    int*   flag  = reinterpret_cast<int*>(smem + SM_FLAG);

    for (int i = tid; i < NDFF; i += 256) {
        ws_s[i] = g_ws[b * NDFF + i];
        V_s[i]  = V[i];
    }

    const float* hB = h + (size_t)blockIdx.x * (MTILE * KDIM);

    // ---- A stream map: one uint4 STS per thread per chunk ----
    const int m_0 = tid >> 2, seg = tid & 3;          // m 0..63, seg 0..3
    const uint32_t a_sts0 = SWZ((m_0 >> 1) * 128 + (m_0 & 1) * 64 + seg * 16);
    const float4* ap0 = reinterpret_cast<const float4*>(hB) + m_0 * 256 + seg * 2;

    // ---- B cp.async map: 8 x 16B per thread per chunk ----
    // idx = it*256 + tid -> row = it*64 + (tid>>2), seg = tid&3
    const uint32_t bdst0 = a_sts0;                     // same formula for row0
    const uint32_t bsrc0 = (uint32_t)(m_0 * KDIM + seg * 8);   // halves

    // ---- ldsm bases (XOR-incremental) ----
    const int r = lane & 7;
    const int selA = (lane >> 3) & 1, selK = (lane >> 4) & 1;
    const int m0f = selA * 8 + r;
    const uint32_t abase0 = SWZ((m0f >> 1) * 128 + (m0f & 1) * 64 + selK * 16);
    const int selKb = (lane >> 3) & 1, selNb = (lane >> 4) & 1;
    const int f0f = selNb * 8 + r;
    const uint32_t bbase0 = SWZ((f0f >> 1) * 128 + (f0f & 1) * 64 + selKb * 16)
                            + (uint32_t)wid * 4096;

    float acc[4][8][4];
#pragma unroll
    for (int mi = 0; mi < 4; mi++)
#pragma unroll
        for (int ni = 0; ni < 8; ni++)
#pragma unroll
            for (int q = 0; q < 4; q++) acc[mi][ni][q] = 0.f;

    float4 p00, p01;

    // ---- prologue: A chunks 0,1 -> stages 0,1; chunk 2 in regs; B chunks 0,1
    p00 = ap0[0]; p01 = ap0[1];
    *reinterpret_cast<uint4*>(smem + SM_A + a_sts0) = cvt8(p00, p01);
    p00 = ap0[8]; p01 = ap0[9];
    *reinterpret_cast<uint4*>(smem + SM_A + 4096 + a_sts0) = cvt8(p00, p01);
    p00 = ap0[16]; p01 = ap0[17];
#pragma unroll
    for (int c = 0; c < 2; c++) {
        uint32_t dst = sb + SM_B + c * 32768 + bdst0;
        const __half* src = g_Uh + bsrc0 + c * KCH;
#pragma unroll
        for (int it = 0; it < 8; it++)
            cp_async16(dst + it * 4096, src + it * (64 * KDIM));
        CP_COMMIT();
    }

    // ---------------- K mainloop ----------------
#pragma unroll 1
    for (int c = 0; c < NCHUNKS; c++) {
        CP_WAIT1();
        __syncthreads();

        if (c + 2 < NCHUNKS) {
            const int st = (c + 2) % 3;
            uint32_t dst = sb + SM_B + st * 32768 + bdst0;
            const __half* src = g_Uh + bsrc0 + (c + 2) * KCH;
#pragma unroll
            for (int it = 0; it < 8; it++)
                cp_async16(dst + it * 4096, src + it * (64 * KDIM));
            *reinterpret_cast<uint4*>(smem + SM_A + st * 4096 + a_sts0)
                = cvt8(p00, p01);
            if (c + 3 < NCHUNKS) {
                p00 = ap0[(c + 3) * 8];
                p01 = ap0[(c + 3) * 8 + 1];
            }
        }
        CP_COMMIT();

        const uint32_t ab = sb + SM_A + (c % 3) * 4096;
        const uint32_t bb = sb + SM_B + (c % 3) * 32768;
#pragma unroll
        for (int ki = 0; ki < 2; ki++) {
            const uint32_t kx = (uint32_t)ki * 32;
            uint32_t af[4][4];
#pragma unroll
            for (int mi = 0; mi < 4; mi++)
                ldsm4(af[mi][0], af[mi][1], af[mi][2], af[mi][3],
                      ab + ((abase0 + mi * 1024) ^ kx));
#pragma unroll
            for (int nj = 0; nj < 4; nj++) {
                uint32_t b0, b1, b2, b3;
                ldsm4(b0, b1, b2, b3, bb + ((bbase0 + nj * 1024) ^ kx));
#pragma unroll
                for (int mi = 0; mi < 4; mi++) {
                    mma16816(acc[mi][2 * nj],     af[mi], b0, b1);
                    mma16816(acc[mi][2 * nj + 1], af[mi], b2, b3);
                }
            }
        }
    }

    // ---------------- epilogue: energy partials ----------------
#pragma unroll
    for (int mi = 0; mi < 4; mi++) {
#pragma unroll
        for (int rh = 0; rh < 2; rh++) {
            float s = 0.f;
#pragma unroll
            for (int nj = 0; nj < 4; nj++) {
#pragma unroll
                for (int jj = 0; jj < 2; jj++) {
#pragma unroll
                    for (int q = 0; q < 2; q++) {
                        int f = wid * 64 + nj * 16 + jj * 8 +
                                ((lane & 3) << 1) + q;
                        float z = ws_s[f] + acc[mi][nj * 2 + jj][rh * 2 + q];
                        z = fminf(fmaxf(z, -15.f), 15.f);
                        float e2 = __expf(2.f * z);
                        float x = __fdividef(e2 - 1.f, e2 + 1.f);
                        s = fmaf(V_s[f], x, s);
                    }
                }
            }
            s += __shfl_xor_sync(0xffffffffu, s, 1);
            s += __shfl_xor_sync(0xffffffffu, s, 2);
            if ((lane & 3) == 0)
                en_s[(wid << 6) + mi * 16 + rh * 8 + (lane >> 2)] = s;
        }
    }

    // ---------------- finalize energy ----------------
    __syncthreads();
    if (tid < MTILE) {
        float e = Vb[0];
#pragma unroll
        for (int w = 0; w < 8; w++) e += en_s[(w << 6) + tid];
        enf_s[tid] = e;
    }
    __syncthreads();

    // ---------------- context partial: sum_m energy[m] * h[m, e] --------------
    {
        const float4* h4 = reinterpret_cast<const float4*>(hB);
        float4 a0 = make_float4(0.f, 0.f, 0.f, 0.f);
#pragma unroll 8
        for (int m = 0; m < MTILE; m++) {
            float en = enf_s[m];
            float4 hv = h4[m * 256 + tid];
            a0.x = fmaf(en, hv.x, a0.x);
            a0.y = fmaf(en, hv.y, a0.y);
            a0.z = fmaf(en, hv.z, a0.z);
            a0.w = fmaf(en, hv.w, a0.w);
        }
        reinterpret_cast<float4*>(g_partial)[((size_t)blockIdx.x << 8) + tid] = a0;
    }

    // ---------------- last CTA per batch reduces (deterministic order) --------
    __threadfence();
    if (tid == 0) {
        int old = atomicAdd(&g_cnt[b], 1);
        *flag = (old == NTILES - 1) ? 1 : 0;
    }
    __syncthreads();
    if (*flag) {
        __threadfence();
        const float4* gp = reinterpret_cast<const float4*>(
            g_partial + ((size_t)b * NTILES) * KDIM);
        float4 a0 = make_float4(0.f, 0.f, 0.f, 0.f);
#pragma unroll 8
        for (int tt = 0; tt < NTILES; tt++) {
            float4 v = gp[tt * 256 + tid];
            a0.x += v.x; a0.y += v.y; a0.z += v.z; a0.w += v.w;
        }
        reinterpret_cast<float4*>(out)[b * 256 + tid] = a0;
    }
}

// ---------------------------------------------------------------------------
extern "C" void kernel_launch(void* const* d_in, const int* in_sizes, int n_in,
                              void* d_out, int out_size) {
    (void)in_sizes; (void)n_in; (void)out_size;
    const float* s  = (const float*)d_in[0];
    const float* h  = (const float*)d_in[1];
    const float* Ww = (const float*)d_in[2];
    const float* Wb = (const float*)d_in[3];
    const float* Uw = (const float*)d_in[4];
    const float* Ub = (const float*)d_in[5];
    const float* Vw = (const float*)d_in[6];
    const float* Vb = (const float*)d_in[7];
    float* out = (float*)d_out;

    cudaFuncSetAttribute(k_main, cudaFuncAttributeMaxDynamicSharedMemorySize,
                         SMEM_TOTAL);

    k_prep<<<577, 256>>>(Uw, s, Ww, Wb, Ub);
    k_main<<<NCTAS, 256, SMEM_TOTAL>>>(h, Vw, Vb, out);
}

// round 8
// speedup vs baseline: 1.2996x; 1.2996x over previous
#include <cuda_runtime.h>
#include <cuda_fp16.h>
#include <cstdint>

// ---------------------------------------------------------------------------
// B=32, T=4096, K=1024 (2H), N=512 (DFF)
// HMMA GEMM, 2 CTAs/SM, 128 threads: warp tile M64 x N64, 2 N-passes of 256.
// R8: software-pipelined ldsm fragments (double-buffered A/B frags).
// ---------------------------------------------------------------------------
#define BATCH   32
#define TSEQ    4096
#define KDIM    1024
#define NDFF    512
#define MTILE   64
#define KCH     32
#define NCHUNKS 32
#define NTILES  (TSEQ / MTILE)     // 64
#define NCTAS   (BATCH * NTILES)   // 2048

__device__ __align__(128) __half g_Uh[NDFF * KDIM];             // 1 MB fp16 U [f][e]
__device__ __align__(128) float  g_ws[BATCH * NDFF];
__device__ __align__(128) float  g_partial[NCTAS * KDIM];       // 8 MB
__device__ int g_cnt[BATCH];

// Shared layout (bytes)
#define SM_WS   0                       // 512 f
#define SM_V    2048                    // 512 f
#define SM_EN   4096                    // 4*64 f
#define SM_ENF  5120                    // 64 f
#define SM_FLAG 5376                    // int
#define SM_A    8192                    // 3 stages x 4096
#define SM_B    20480                   // 3 stages x 16384
#define SMEM_TOTAL 69632

#define SWZ(off) ((uint32_t)(off) ^ ((((uint32_t)(off)) >> 3) & 0x70u))

__device__ __forceinline__ uint32_t smem_u32(const void* p) {
    uint32_t a;
    asm("{ .reg .u64 t; cvta.to.shared.u64 t, %1; cvt.u32.u64 %0, t; }"
        : "=r"(a) : "l"(p));
    return a;
}
__device__ __forceinline__ void cp_async16(uint32_t dst, const void* src) {
    asm volatile("cp.async.cg.shared.global [%0], [%1], 16;"
                 :: "r"(dst), "l"(src) : "memory");
}
#define CP_COMMIT() asm volatile("cp.async.commit_group;" ::: "memory")
#define CP_WAIT1()  asm volatile("cp.async.wait_group 1;" ::: "memory")

__device__ __forceinline__ void ldsm4(uint32_t& r0, uint32_t& r1, uint32_t& r2,
                                      uint32_t& r3, uint32_t addr) {
    asm volatile("ldmatrix.sync.aligned.m8n8.x4.shared.b16 {%0,%1,%2,%3}, [%4];"
                 : "=r"(r0), "=r"(r1), "=r"(r2), "=r"(r3) : "r"(addr));
}
__device__ __forceinline__ void mma16816(float* c, const uint32_t* a,
                                         uint32_t b0, uint32_t b1) {
    asm volatile(
        "mma.sync.aligned.m16n8k16.row.col.f32.f16.f16.f32 "
        "{%0,%1,%2,%3}, {%4,%5,%6,%7}, {%8,%9}, {%0,%1,%2,%3};"
        : "+f"(c[0]), "+f"(c[1]), "+f"(c[2]), "+f"(c[3])
        : "r"(a[0]), "r"(a[1]), "r"(a[2]), "r"(a[3]), "r"(b0), "r"(b1));
}
__device__ __forceinline__ uint4 cvt8(const float4& x, const float4& y) {
    uint4 u; __half2 t;
    t = __floats2half2_rn(x.x, x.y); u.x = *(uint32_t*)&t;
    t = __floats2half2_rn(x.z, x.w); u.y = *(uint32_t*)&t;
    t = __floats2half2_rn(y.x, y.y); u.z = *(uint32_t*)&t;
    t = __floats2half2_rn(y.z, y.w); u.w = *(uint32_t*)&t;
    return u;
}

// ---------------------------------------------------------------------------
// Fused prep: blocks 0..511 convU, 512..575 ws, 576 zero counters
// ---------------------------------------------------------------------------
__global__ void k_prep(const float* __restrict__ Uw, const float* __restrict__ s,
                       const float* __restrict__ W,  const float* __restrict__ Wb,
                       const float* __restrict__ Ub) {
    int blk = blockIdx.x;
    int tid = threadIdx.x;
    if (blk < 512) {
        int i = blk * 256 + tid;
        float4 v = reinterpret_cast<const float4*>(Uw)[i];
        __half2 p0 = __floats2half2_rn(v.x, v.y);
        __half2 p1 = __floats2half2_rn(v.z, v.w);
        uint2 u;
        u.x = *reinterpret_cast<uint32_t*>(&p0);
        u.y = *reinterpret_cast<uint32_t*>(&p1);
        *reinterpret_cast<uint2*>(&g_Uh[i * 4]) = u;
    } else if (blk < 576) {
        __shared__ float ssh[512];
        int q = blk - 512;
        int b = q >> 1;
        int f = ((q & 1) << 8) + tid;
        ssh[tid]       = s[b * 512 + tid];
        ssh[tid + 256] = s[b * 512 + tid + 256];
        __syncthreads();
        float acc = Wb[f] + Ub[f];
        const float4* Wr = reinterpret_cast<const float4*>(W + (size_t)f * 512);
#pragma unroll 4
        for (int e4 = 0; e4 < 128; e4++) {
            float4 w = Wr[e4];
            acc = fmaf(ssh[e4 * 4 + 0], w.x, acc);
            acc = fmaf(ssh[e4 * 4 + 1], w.y, acc);
            acc = fmaf(ssh[e4 * 4 + 2], w.z, acc);
            acc = fmaf(ssh[e4 * 4 + 3], w.w, acc);
        }
        g_ws[b * 512 + f] = acc;
    } else {
        if (tid < BATCH) g_cnt[tid] = 0;
    }
}

// ---------------------------------------------------------------------------
// Main kernel: 128 threads, 4 warps, warp tile M64 x N64, 2 CTAs/SM.
// Packed smem rows: two 64B k-rows per 128B smem row, SW128-swizzled.
// ---------------------------------------------------------------------------
__global__ __launch_bounds__(128, 2)
void k_main(const float* __restrict__ h, const float* __restrict__ V,
            const float* __restrict__ Vb, float* __restrict__ out) {
    extern __shared__ char smem[];
    const uint32_t sb = smem_u32(smem);
    const int tid  = threadIdx.x;
    const int wid  = tid >> 5;     // = ng, 0..3
    const int lane = tid & 31;
    const int b    = blockIdx.x >> 6;

    float* ws_s  = reinterpret_cast<float*>(smem + SM_WS);
    float* V_s   = reinterpret_cast<float*>(smem + SM_V);
    float* en_s  = reinterpret_cast<float*>(smem + SM_EN);
    float* enf_s = reinterpret_cast<float*>(smem + SM_ENF);
    int*   flag  = reinterpret_cast<int*>(smem + SM_FLAG);

    for (int i = tid; i < NDFF; i += 128) {
        ws_s[i] = g_ws[b * NDFF + i];
        V_s[i]  = V[i];
    }
    for (int i = tid; i < 4 * MTILE; i += 128) en_s[i] = 0.f;

    const float* hB = h + (size_t)blockIdx.x * (MTILE * KDIM);

    // A stream map
    const int m_0 = tid >> 2, seg = tid & 3;
    const uint32_t a_sts0 = SWZ((m_0 >> 1) * 128 + (m_0 & 1) * 64 + seg * 16);
    const float4* ap0 = reinterpret_cast<const float4*>(hB) + m_0 * 256 + seg * 2;
    const float4* ap1 = ap0 + 32 * 256;

    // B cp.async map
    const uint32_t bdst0 = a_sts0;
    const uint32_t bsrc0 = (uint32_t)(m_0 * KDIM + seg * 8);

    // ldsm bases (XOR-incremental)
    const int r = lane & 7;
    const int selA = (lane >> 3) & 1, selK = (lane >> 4) & 1;
    const int m0f = selA * 8 + r;
    const uint32_t abase0 = SWZ((m0f >> 1) * 128 + (m0f & 1) * 64 + selK * 16);
    const int selKb = (lane >> 3) & 1, selNb = (lane >> 4) & 1;
    const int f0f = selNb * 8 + r;
    const uint32_t bbase0 = SWZ((f0f >> 1) * 128 + (f0f & 1) * 64 + selKb * 16)
                            + (uint32_t)wid * 4096;

    float4 p00, p01, p10, p11;

    // ======================= two N-passes of 256 =======================
#pragma unroll 1
    for (int np = 0; np < 2; np++) {
        const __half* Ub2 = g_Uh + (size_t)(np * 256) * KDIM;

        float acc[4][8][4];
#pragma unroll
        for (int mi = 0; mi < 4; mi++)
#pragma unroll
            for (int ni = 0; ni < 8; ni++)
#pragma unroll
                for (int q = 0; q < 4; q++) acc[mi][ni][q] = 0.f;

        __syncthreads();

        // prologue: A chunks 0,1 -> stages 0,1; chunk 2 in regs; B chunks 0,1
        p00 = ap0[0];  p01 = ap0[1];  p10 = ap1[0];  p11 = ap1[1];
        *reinterpret_cast<uint4*>(smem + SM_A + a_sts0)        = cvt8(p00, p01);
        *reinterpret_cast<uint4*>(smem + SM_A + a_sts0 + 2048) = cvt8(p10, p11);
        p00 = ap0[8];  p01 = ap0[9];  p10 = ap1[8];  p11 = ap1[9];
        *reinterpret_cast<uint4*>(smem + SM_A + 4096 + a_sts0)        = cvt8(p00, p01);
        *reinterpret_cast<uint4*>(smem + SM_A + 4096 + a_sts0 + 2048) = cvt8(p10, p11);
        p00 = ap0[16]; p01 = ap0[17]; p10 = ap1[16]; p11 = ap1[17];
#pragma unroll
        for (int c = 0; c < 2; c++) {
            uint32_t dst = sb + SM_B + c * 16384 + bdst0;
            const __half* src = Ub2 + bsrc0 + c * KCH;
#pragma unroll
            for (int it = 0; it < 8; it++)
                cp_async16(dst + it * 2048, src + it * (32 * KDIM));
            CP_COMMIT();
        }

        // ---------------- K mainloop (fragment-pipelined) ----------------
#pragma unroll 1
        for (int c = 0; c < NCHUNKS; c++) {
            CP_WAIT1();
            __syncthreads();

            const uint32_t ab = sb + SM_A + (c % 3) * 4096;
            const uint32_t bbs = sb + SM_B + (c % 3) * 16384;

            // fragment prologue: A[ki=0] (4x) and B[ki=0,nj=0]
            uint32_t af[2][4][4];
            uint32_t bf[2][4];
#pragma unroll
            for (int mi = 0; mi < 4; mi++)
                ldsm4(af[0][mi][0], af[0][mi][1], af[0][mi][2], af[0][mi][3],
                      ab + (abase0 + mi * 1024));
            ldsm4(bf[0][0], bf[0][1], bf[0][2], bf[0][3], bbs + bbase0);

            // overlap: issue gmem prefetch for chunk c+2 under ldsm latency
            if (c + 2 < NCHUNKS) {
                const int st = (c + 2) % 3;
                uint32_t dst = sb + SM_B + st * 16384 + bdst0;
                const __half* src = Ub2 + bsrc0 + (c + 2) * KCH;
#pragma unroll
                for (int it = 0; it < 8; it++)
                    cp_async16(dst + it * 2048, src + it * (32 * KDIM));
                *reinterpret_cast<uint4*>(smem + SM_A + st * 4096 + a_sts0)
                    = cvt8(p00, p01);
                *reinterpret_cast<uint4*>(smem + SM_A + st * 4096 + a_sts0 + 2048)
                    = cvt8(p10, p11);
                if (c + 3 < NCHUNKS) {
                    p00 = ap0[(c + 3) * 8];     p01 = ap0[(c + 3) * 8 + 1];
                    p10 = ap1[(c + 3) * 8];     p11 = ap1[(c + 3) * 8 + 1];
                }
            }
            CP_COMMIT();

            // pipelined MMA stream: prefetch next B (or next-ki A+B) before use
#pragma unroll
            for (int ki = 0; ki < 2; ki++) {
                const uint32_t kx = (uint32_t)ki * 32;
#pragma unroll
                for (int nj = 0; nj < 4; nj++) {
                    const int cur = nj & 1;
                    const int nxt = cur ^ 1;
                    if (nj < 3) {
                        ldsm4(bf[nxt][0], bf[nxt][1], bf[nxt][2], bf[nxt][3],
                              bbs + ((bbase0 + (nj + 1) * 1024) ^ kx));
                    } else if (ki == 0) {
#pragma unroll
                        for (int mi = 0; mi < 4; mi++)
                            ldsm4(af[1][mi][0], af[1][mi][1],
                                  af[1][mi][2], af[1][mi][3],
                                  ab + ((abase0 + mi * 1024) ^ 32));
                        ldsm4(bf[nxt][0], bf[nxt][1], bf[nxt][2], bf[nxt][3],
                              bbs + (bbase0 ^ 32));
                    }
#pragma unroll
                    for (int mi = 0; mi < 4; mi++) {
                        mma16816(acc[mi][2 * nj],     af[ki][mi], bf[cur][0], bf[cur][1]);
                        mma16816(acc[mi][2 * nj + 1], af[ki][mi], bf[cur][2], bf[cur][3]);
                    }
                }
            }
        }

        // ---------------- epilogue: energy partials ----------------
#pragma unroll
        for (int mi = 0; mi < 4; mi++) {
#pragma unroll
            for (int rh = 0; rh < 2; rh++) {
                float s = 0.f;
#pragma unroll
                for (int nj = 0; nj < 4; nj++) {
#pragma unroll
                    for (int jj = 0; jj < 2; jj++) {
#pragma unroll
                        for (int q = 0; q < 2; q++) {
                            int f = np * 256 + wid * 64 + nj * 16 + jj * 8 +
                                    ((lane & 3) << 1) + q;
                            float z = ws_s[f] + acc[mi][nj * 2 + jj][rh * 2 + q];
                            z = fminf(fmaxf(z, -15.f), 15.f);
                            float e2 = __expf(2.f * z);
                            float x = __fdividef(e2 - 1.f, e2 + 1.f);
                            s = fmaf(V_s[f], x, s);
                        }
                    }
                }
                s += __shfl_xor_sync(0xffffffffu, s, 1);
                s += __shfl_xor_sync(0xffffffffu, s, 2);
                if ((lane & 3) == 0)
                    en_s[(wid << 6) + mi * 16 + rh * 8 + (lane >> 2)] += s;
            }
        }
    }

    // ---------------- finalize energy ----------------
    __syncthreads();
    if (tid < MTILE) {
        float e = Vb[0];
#pragma unroll
        for (int w = 0; w < 4; w++) e += en_s[(w << 6) + tid];
        enf_s[tid] = e;
    }
    __syncthreads();

    // ---------------- context partial: sum_m energy[m] * h[m, e] --------------
    {
        const float4* h4 = reinterpret_cast<const float4*>(hB);
        float4 a0 = make_float4(0.f, 0.f, 0.f, 0.f);
        float4 a1 = make_float4(0.f, 0.f, 0.f, 0.f);
#pragma unroll 8
        for (int m = 0; m < MTILE; m++) {
            float en = enf_s[m];
            float4 v0 = h4[m * 256 + tid * 2];
            float4 v1 = h4[m * 256 + tid * 2 + 1];
            a0.x = fmaf(en, v0.x, a0.x); a0.y = fmaf(en, v0.y, a0.y);
            a0.z = fmaf(en, v0.z, a0.z); a0.w = fmaf(en, v0.w, a0.w);
            a1.x = fmaf(en, v1.x, a1.x); a1.y = fmaf(en, v1.y, a1.y);
            a1.z = fmaf(en, v1.z, a1.z); a1.w = fmaf(en, v1.w, a1.w);
        }
        float4* gp = reinterpret_cast<float4*>(g_partial) +
                     ((size_t)blockIdx.x << 8);
        gp[tid * 2]     = a0;
        gp[tid * 2 + 1] = a1;
    }

    // ---------------- last CTA per batch reduces (deterministic order) --------
    __threadfence();
    if (tid == 0) {
        int old = atomicAdd(&g_cnt[b], 1);
        *flag = (old == NTILES - 1) ? 1 : 0;
    }
    __syncthreads();
    if (*flag) {
        __threadfence();
        const float4* gp = reinterpret_cast<const float4*>(
            g_partial + ((size_t)b * NTILES) * KDIM);
        float4 a0 = make_float4(0.f, 0.f, 0.f, 0.f);
        float4 a1 = make_float4(0.f, 0.f, 0.f, 0.f);
#pragma unroll 8
        for (int tt = 0; tt < NTILES; tt++) {
            float4 v0 = gp[tt * 256 + tid * 2];
            float4 v1 = gp[tt * 256 + tid * 2 + 1];
            a0.x += v0.x; a0.y += v0.y; a0.z += v0.z; a0.w += v0.w;
            a1.x += v1.x; a1.y += v1.y; a1.z += v1.z; a1.w += v1.w;
        }
        float4* o4 = reinterpret_cast<float4*>(out) + b * 256;
        o4[tid * 2]     = a0;
        o4[tid * 2 + 1] = a1;
    }
}

// ---------------------------------------------------------------------------
extern "C" void kernel_launch(void* const* d_in, const int* in_sizes, int n_in,
                              void* d_out, int out_size) {
    (void)in_sizes; (void)n_in; (void)out_size;
    const float* s  = (const float*)d_in[0];
    const float* h  = (const float*)d_in[1];
    const float* Ww = (const float*)d_in[2];
    const float* Wb = (const float*)d_in[3];
    const float* Uw = (const float*)d_in[4];
    const float* Ub = (const float*)d_in[5];
    const float* Vw = (const float*)d_in[6];
    const float* Vb = (const float*)d_in[7];
    float* out = (float*)d_out;

    cudaFuncSetAttribute(k_main, cudaFuncAttributeMaxDynamicSharedMemorySize,
                         SMEM_TOTAL);

    k_prep<<<577, 256>>>(Uw, s, Ww, Wb, Ub);
    k_main<<<NCTAS, 128, SMEM_TOTAL>>>(h, Vw, Vb, out);
}